// round 1
// baseline (speedup 1.0000x reference)
#include <cuda_runtime.h>
#include <cuda_bf16.h>

// NCEAverage: B=256, D=128, N=1e6, K1=2048, T=0.07, MOMENTUM=0.5
// Inputs  : l[B,D] f32, ab[B,D] f32, y[B] i32, idx[B,K1] i32,
//           memory_l[N,D] f32, memory_ab[N,D] f32
// Output  : [ out_l(B*K1) | out_ab(B*K1) | new_memory_l(N*D) | new_memory_ab(N*D) ]

#define DIM 128
#define T_INV (1.0f / 0.07f)

// ---------------------------------------------------------------------------
// Scoring: one warp per (b,k). Both banks' dots fused per warp.
// out_ab[b,k] = dot(memory_l[idx[b,k]], ab[b]) / T
// out_l [b,k] = dot(memory_ab[idx[b,k]], l[b]) / T
// ---------------------------------------------------------------------------
__global__ void __launch_bounds__(256) score_kernel(
    const float* __restrict__ l, const float* __restrict__ ab,
    const int* __restrict__ idx,
    const float* __restrict__ mem_l, const float* __restrict__ mem_ab,
    float* __restrict__ out_l, float* __restrict__ out_ab, int K1)
{
    const int b = blockIdx.y;
    __shared__ float l_s[DIM];
    __shared__ float ab_s[DIM];
    const int tid = threadIdx.x;
    if (tid < DIM)       l_s[tid]        = l[b * DIM + tid];
    else                 ab_s[tid - DIM] = ab[b * DIM + (tid - DIM)];
    __syncthreads();

    const int warp = tid >> 5;
    const int lane = tid & 31;
    const int k    = blockIdx.x * 8 + warp;

    const long long row = idx[(long long)b * K1 + k];
    const float4 wl  = ((const float4*)(mem_l  + row * DIM))[lane];
    const float4 wab = ((const float4*)(mem_ab + row * DIM))[lane];
    const float4 qab = ((const float4*)ab_s)[lane];
    const float4 ql  = ((const float4*)l_s)[lane];

    float s_ab = wl.x * qab.x + wl.y * qab.y + wl.z * qab.z + wl.w * qab.w;
    float s_l  = wab.x * ql.x + wab.y * ql.y + wab.z * ql.z + wab.w * ql.w;

    #pragma unroll
    for (int off = 16; off; off >>= 1) {
        s_ab += __shfl_xor_sync(0xffffffffu, s_ab, off);
        s_l  += __shfl_xor_sync(0xffffffffu, s_l,  off);
    }
    if (lane == 0) {
        const long long o = (long long)b * K1 + k;
        out_ab[o] = s_ab * T_INV;
        out_l[o]  = s_l  * T_INV;
    }
}

// ---------------------------------------------------------------------------
// EMA + L2-normalize + scatter (last occurrence wins on duplicate y).
// One block (128 threads) per batch element; runs AFTER the full-bank copy.
// ---------------------------------------------------------------------------
__global__ void __launch_bounds__(DIM) update_kernel(
    const float* __restrict__ l, const float* __restrict__ ab,
    const int* __restrict__ y,
    const float* __restrict__ mem_l, const float* __restrict__ mem_ab,
    float* __restrict__ out_ml, float* __restrict__ out_mab, int B)
{
    const int b   = blockIdx.x;
    const int tid = threadIdx.x;

    __shared__ int skip;
    if (tid == 0) {
        const int yy = y[b];
        int s = 0;
        for (int bb = b + 1; bb < B; ++bb)
            if (y[bb] == yy) { s = 1; break; }
        skip = s;
    }
    __syncthreads();
    if (skip) return;

    const long long row = y[b];
    const float vl  = 0.5f * mem_l [row * DIM + tid] + 0.5f * l [b * DIM + tid];
    const float vab = 0.5f * mem_ab[row * DIM + tid] + 0.5f * ab[b * DIM + tid];

    float sl = vl * vl, sab = vab * vab;
    #pragma unroll
    for (int off = 16; off; off >>= 1) {
        sl  += __shfl_xor_sync(0xffffffffu, sl,  off);
        sab += __shfl_xor_sync(0xffffffffu, sab, off);
    }
    __shared__ float wsl[4], wsab[4];
    const int w = tid >> 5, lane = tid & 31;
    if (lane == 0) { wsl[w] = sl; wsab[w] = sab; }
    __syncthreads();
    const float tsl  = wsl[0]  + wsl[1]  + wsl[2]  + wsl[3];
    const float tsab = wsab[0] + wsab[1] + wsab[2] + wsab[3];

    out_ml [row * DIM + tid] = vl  / sqrtf(tsl);
    out_mab[row * DIM + tid] = vab / sqrtf(tsab);
}

extern "C" void kernel_launch(void* const* d_in, const int* in_sizes, int n_in,
                              void* d_out, int out_size)
{
    const float* l      = (const float*)d_in[0];
    const float* ab     = (const float*)d_in[1];
    const int*   y      = (const int*)  d_in[2];
    const int*   idx    = (const int*)  d_in[3];
    const float* mem_l  = (const float*)d_in[4];
    const float* mem_ab = (const float*)d_in[5];

    const int       B  = in_sizes[2];
    const int       K1 = in_sizes[3] / B;
    const long long ND = (long long)in_sizes[4];
    const long long BK = (long long)B * K1;

    float* out = (float*)d_out;
    float* out_l   = out;
    float* out_ab  = out + BK;
    float* out_ml  = out + 2 * BK;
    float* out_mab = out + 2 * BK + ND;

    // 1) Passthrough copy of both memory banks (dominant cost, ~2 GB traffic).
    cudaMemcpyAsync(out_ml,  mem_l,  ND * sizeof(float), cudaMemcpyDeviceToDevice);
    cudaMemcpyAsync(out_mab, mem_ab, ND * sizeof(float), cudaMemcpyDeviceToDevice);

    // 2) Scoring (reads OLD memory from inputs — independent of the copy on
    //    this stream's order, but serialized after it; revisit for overlap).
    dim3 sgrid(K1 / 8, B);
    score_kernel<<<sgrid, 256>>>(l, ab, idx, mem_l, mem_ab, out_l, out_ab, K1);

    // 3) Overwrite the B updated rows in the copied banks (after the copy).
    update_kernel<<<B, DIM>>>(l, ab, y, mem_l, mem_ab, out_ml, out_mab, B);
}